// round 10
// baseline (speedup 1.0000x reference)
#include <cuda_runtime.h>
#include <cuda_fp16.h>
#include <cstdint>

#define E_   8
#define CAP_ 2048
#define D_   1024
#define H_   4096

// ---------------- scratch (device globals; no runtime allocation) ----------------
__device__ __half g_Xh [(size_t)E_ * CAP_ * D_];   // [E*2048][1024]
__device__ __half g_W1h[(size_t)E_ * H_   * D_];   // [E*4096][1024]
__device__ __half g_W2T[(size_t)E_ * D_   * H_];   // [E*1024][4096]  (W2^T)
__device__ __half g_Y  [(size_t)E_ * CAP_ * H_];   // [E*2048][4096]

// ---------------- PTX helpers (portable: sm_80+ features only) ----------------
__device__ __forceinline__ uint32_t smem_u32(const void* p) {
    uint32_t a;
    asm("{ .reg .u64 t; cvta.to.shared.u64 t, %1; cvt.u32.u64 %0, t; }" : "=r"(a) : "l"(p));
    return a;
}
__device__ __forceinline__ void cpa16(uint32_t s, const void* g) {
    asm volatile("cp.async.cg.shared.global [%0], [%1], 16;" :: "r"(s), "l"(g) : "memory");
}
__device__ __forceinline__ void ldsm4(uint32_t r[4], uint32_t addr) {
    asm volatile("ldmatrix.sync.aligned.m8n8.x4.shared.b16 {%0,%1,%2,%3}, [%4];"
                 : "=r"(r[0]), "=r"(r[1]), "=r"(r[2]), "=r"(r[3]) : "r"(addr));
}
__device__ __forceinline__ void mma16816(float d[4], const uint32_t a[4],
                                         uint32_t b0, uint32_t b1) {
    asm volatile("mma.sync.aligned.m16n8k16.row.col.f32.f16.f16.f32 "
                 "{%0,%1,%2,%3},{%4,%5,%6,%7},{%8,%9},{%0,%1,%2,%3};"
                 : "+f"(d[0]), "+f"(d[1]), "+f"(d[2]), "+f"(d[3])
                 : "r"(a[0]), "r"(a[1]), "r"(a[2]), "r"(a[3]), "r"(b0), "r"(b1));
}
__device__ __forceinline__ uint32_t h2u(__half2 h) {
    return *reinterpret_cast<uint32_t*>(&h);
}

// ---------------- convert: fp32 -> fp16 elementwise; dst chosen in DEVICE code ----------------
template<int TGT>   // 0 -> g_Xh, 1 -> g_W1h
__global__ void conv_f16(const float* __restrict__ src) {
    __half* dst = (TGT == 0) ? g_Xh : g_W1h;
    size_t t = (size_t)blockIdx.x * 256 + threadIdx.x;   // one float4 per thread
    float4 v = *((const float4*)src + t);
    __half2 h0 = __floats2half2_rn(v.x, v.y);
    __half2 h1 = __floats2half2_rn(v.z, v.w);
    *(uint2*)(dst + t * 4) = make_uint2(h2u(h0), h2u(h1));
}

// ---------------- W2 transpose + convert: [E,H,D] fp32 -> [E,D][H] fp16 ----------------
__global__ void conv_w2t(const float* __restrict__ w2) {
    __shared__ float tile[32][33];
    int e  = blockIdx.z;
    int d0 = blockIdx.x * 32;
    int h0 = blockIdx.y * 32;
    int tx = threadIdx.x, ty = threadIdx.y;
#pragma unroll
    for (int r = 0; r < 4; r++) {
        int h = h0 + ty + r * 8;
        tile[ty + r * 8][tx] = w2[((size_t)(e * H_ + h)) * D_ + d0 + tx];
    }
    __syncthreads();
#pragma unroll
    for (int r = 0; r < 4; r++) {
        int d = d0 + ty + r * 8;
        int h = h0 + tx;
        g_W2T[((size_t)(e * D_ + d)) * H_ + h] = __float2half_rn(tile[tx][ty + r * 8]);
    }
}

// ---------------- fp16 GEMM via mma.sync (cp.async pipeline), R8 mainloop ----------------
// 128 threads, 4 warps in a 2x2 grid, 3 smem stages, 2 CTAs/SM.
// PHASE 1: 128x128 CTA / 64x64 warp tiles.
// PHASE 2: 128x64  CTA / 64x32 warp tiles  (2048 CTAs -> 6.9 waves, ~1% tail).
template<int PHASE, int TM, int TN, int WM, int WN>
__global__ void __launch_bounds__(128, 2) gemm_mma(const float* __restrict__ bias,
                                                   float* __restrict__ outF) {
    static_assert(TM / WM == 2 && TN / WN == 2, "warp grid must be 2x2");
    constexpr int Ntot = (PHASE == 1) ? H_ : D_;
    constexpr int KSEG = (PHASE == 1) ? D_ : H_;
    constexpr int NCH  = KSEG / 64;        // 64-wide K chunks
    constexpr int Mt   = CAP_ / TM;
    constexpr int Nt   = Ntot / TN;
    constexpr int NSTAGE = 3;
    constexpr int STB  = (TM + TN) * 128;  // bytes per stage
    constexpr int WROWS = WM / 16, WCOLS = WN / 8, BT16 = WN / 16;

    extern __shared__ char smem[];
    const uint32_t sb = smem_u32(smem);
    const int tid = threadIdx.x, wid = tid >> 5, lane = tid & 31;

    const int idx = blockIdx.x;
    const int mt = idx % Mt;
    const int nt = (idx / Mt) % Nt;
    const int e  = idx / (Mt * Nt);
    const int m0 = mt * TM, n0 = nt * TN;

    const __half* A = (PHASE == 1) ? g_Xh  : g_Y;
    const __half* B = (PHASE == 1) ? g_W1h : g_W2T;
    const __half* Ab = A + (size_t)(e * CAP_ + m0) * KSEG;
    const __half* Bb = B + (size_t)(e * Ntot + n0) * KSEG;

    auto issue = [&](int c) {
        const int k0 = c * 64;
        const int st = c % NSTAGE;
        const uint32_t sA = sb + st * STB, sB = sA + TM * 128;
#pragma unroll
        for (int t = 0; t < TM / 16; t++) {            // A: TM*8 chunks / 128 thr
            int i = t * 128 + tid, row = i >> 3, c16 = i & 7;
            cpa16(sA + row * 128 + ((c16 ^ (row & 7)) << 4),
                  Ab + (size_t)row * KSEG + k0 + c16 * 8);
        }
#pragma unroll
        for (int t = 0; t < TN / 16; t++) {            // B: TN*8 chunks / 128 thr
            int i = t * 128 + tid, row = i >> 3, c16 = i & 7;
            cpa16(sB + row * 128 + ((c16 ^ (row & 7)) << 4),
                  Bb + (size_t)row * KSEG + k0 + c16 * 8);
        }
        asm volatile("cp.async.commit_group;" ::: "memory");
    };

    const int m_off = (wid >> 1) * WM;     // 2x2 warp grid
    const int n_off = (wid & 1) * WN;
    float acc[WROWS][WCOLS][4] = {};

    issue(0);
    issue(1);
    asm volatile("cp.async.wait_group 1;" ::: "memory");
    __syncthreads();

    for (int c = 0; c < NCH; ++c) {
        const int st = c % NSTAGE;
        const uint32_t sA = sb + st * STB, sB = sA + TM * 128;
#pragma unroll
        for (int kk = 0; kk < 4; ++kk) {               // 4 x k16 per 64-chunk
            uint32_t aF[WROWS][4];
#pragma unroll
            for (int i = 0; i < WROWS; ++i) {
                int row = m_off + 16 * i + (lane & 15);
                int ch  = kk * 2 + (lane >> 4);
                ldsm4(aF[i], sA + row * 128 + ((ch ^ (row & 7)) << 4));
            }
            uint32_t bF[BT16][4];
#pragma unroll
            for (int j4 = 0; j4 < BT16; ++j4) {
                int row = n_off + 16 * j4 + ((lane >> 4) << 3) + (lane & 7);
                int ch  = kk * 2 + ((lane >> 3) & 1);
                ldsm4(bF[j4], sB + row * 128 + ((ch ^ (row & 7)) << 4));
            }
#pragma unroll
            for (int i = 0; i < WROWS; ++i)
#pragma unroll
                for (int j = 0; j < WCOLS; ++j)
                    mma16816(acc[i][j], aF[i], bF[j >> 1][(j & 1) * 2], bF[j >> 1][(j & 1) * 2 + 1]);
        }
        if (c + 2 < NCH) issue(c + 2);
        else asm volatile("cp.async.commit_group;" ::: "memory");
        asm volatile("cp.async.wait_group 1;" ::: "memory");
        __syncthreads();
    }

    // ---- epilogue ----
    const int r_lane = lane >> 2;
    const int c_lane = (lane & 3) * 2;
    const float* brow = bias + (size_t)e * Ntot;
#pragma unroll
    for (int i = 0; i < WROWS; ++i) {
#pragma unroll
        for (int half = 0; half < 2; ++half) {
            const int m = m0 + m_off + 16 * i + r_lane + half * 8;
            if (PHASE == 1) {
                __half* yrow = g_Y + (size_t)(e * CAP_ + m) * H_;
#pragma unroll
                for (int j = 0; j < WCOLS; ++j) {
                    const int col = n0 + n_off + 8 * j + c_lane;
                    float v0 = acc[i][j][half * 2 + 0] + brow[col];
                    float v1 = acc[i][j][half * 2 + 1] + brow[col + 1];
                    v0 = fmaxf(v0, 0.f);
                    v1 = fmaxf(v1, 0.f);
                    *(uint32_t*)(yrow + col) = h2u(__floats2half2_rn(v0, v1));
                }
            } else {
                float* orow = outF + (size_t)(e * CAP_ + m) * D_;
#pragma unroll
                for (int j = 0; j < WCOLS; ++j) {
                    const int col = n0 + n_off + 8 * j + c_lane;
                    float2 f;
                    f.x = acc[i][j][half * 2 + 0] + brow[col];
                    f.y = acc[i][j][half * 2 + 1] + brow[col + 1];
                    *(float2*)(orow + col) = f;
                }
            }
        }
    }
}

// ---------------- launch ----------------
extern "C" void kernel_launch(void* const* d_in, const int* in_sizes, int n_in,
                              void* d_out, int out_size) {
    const float* x  = (const float*)d_in[0];   // [E, CAP, D]
    const float* w1 = (const float*)d_in[1];   // [E, H, D]
    const float* b1 = (const float*)d_in[2];   // [E, H]
    const float* w2 = (const float*)d_in[3];   // [E, H, D]
    const float* b2 = (const float*)d_in[4];   // [E, D]
    float* out = (float*)d_out;                // [E, CAP, D]

    // GEMM1: 128x128 CTA / 64x64 warp tiles (R8 config, best measured)
    auto g1 = gemm_mma<1, 128, 128, 64, 64>;
    constexpr int SM1 = 3 * (128 + 128) * 128;   // 96 KB
    // GEMM2: 128x64 CTA / 64x32 warp tiles -> 2048 CTAs, ~1% tail
    auto g2 = gemm_mma<2, 128, 64, 64, 32>;
    constexpr int SM2 = 3 * (128 + 64) * 128;    // 72 KB

    cudaFuncSetAttribute(g1, cudaFuncAttributeMaxDynamicSharedMemorySize, SM1);
    cudaFuncSetAttribute(g2, cudaFuncAttributeMaxDynamicSharedMemorySize, SM2);

    // 1) conversions (destinations resolved in device code)
    conv_f16<0><<<(E_ * CAP_ * D_ / 4) / 256, 256>>>(x);           // X  -> g_Xh
    conv_f16<1><<<(E_ * H_   * D_ / 4) / 256, 256>>>(w1);          // W1 -> g_W1h
    conv_w2t<<<dim3(D_ / 32, H_ / 32, E_), dim3(32, 8)>>>(w2);     // W2 -> g_W2T (transposed)

    // 2) GEMM1: relu(X W1^T + b1) -> g_Y (fp16)
    g1<<<(CAP_ / 128) * (H_ / 128) * E_, 128, SM1>>>(b1, nullptr);

    // 3) GEMM2: Y W2 + b2 -> out (fp32)
    g2<<<(CAP_ / 128) * (D_ / 64) * E_, 128, SM2>>>(b2, out);
}

// round 11
// speedup vs baseline: 1.0044x; 1.0044x over previous
#include <cuda_runtime.h>
#include <cuda_fp16.h>
#include <cstdint>

#define E_   8
#define CAP_ 2048
#define D_   1024
#define H_   4096

// ---------------- scratch (device globals; no runtime allocation) ----------------
__device__ __half g_Xh [(size_t)E_ * CAP_ * D_];   // [E*2048][1024]
__device__ __half g_W1h[(size_t)E_ * H_   * D_];   // [E*4096][1024]
__device__ __half g_W2T[(size_t)E_ * D_   * H_];   // [E*1024][4096]  (W2^T)
__device__ __half g_Y  [(size_t)E_ * CAP_ * H_];   // [E*2048][4096]
__device__ float  g_P  [(size_t)E_ * CAP_ * D_];   // GEMM2 k-slice-1 partials (fp32)

// ---------------- PTX helpers (portable: sm_80+ features only) ----------------
__device__ __forceinline__ uint32_t smem_u32(const void* p) {
    uint32_t a;
    asm("{ .reg .u64 t; cvta.to.shared.u64 t, %1; cvt.u32.u64 %0, t; }" : "=r"(a) : "l"(p));
    return a;
}
__device__ __forceinline__ void cpa16(uint32_t s, const void* g) {
    asm volatile("cp.async.cg.shared.global [%0], [%1], 16;" :: "r"(s), "l"(g) : "memory");
}
__device__ __forceinline__ void ldsm4(uint32_t r[4], uint32_t addr) {
    asm volatile("ldmatrix.sync.aligned.m8n8.x4.shared.b16 {%0,%1,%2,%3}, [%4];"
                 : "=r"(r[0]), "=r"(r[1]), "=r"(r[2]), "=r"(r[3]) : "r"(addr));
}
__device__ __forceinline__ void mma16816(float d[4], const uint32_t a[4],
                                         uint32_t b0, uint32_t b1) {
    asm volatile("mma.sync.aligned.m16n8k16.row.col.f32.f16.f16.f32 "
                 "{%0,%1,%2,%3},{%4,%5,%6,%7},{%8,%9},{%0,%1,%2,%3};"
                 : "+f"(d[0]), "+f"(d[1]), "+f"(d[2]), "+f"(d[3])
                 : "r"(a[0]), "r"(a[1]), "r"(a[2]), "r"(a[3]), "r"(b0), "r"(b1));
}
__device__ __forceinline__ uint32_t h2u(__half2 h) {
    return *reinterpret_cast<uint32_t*>(&h);
}

// ---------------- convert: fp32 -> fp16 elementwise; dst chosen in DEVICE code ----------------
template<int TGT>   // 0 -> g_Xh, 1 -> g_W1h
__global__ void conv_f16(const float* __restrict__ src) {
    __half* dst = (TGT == 0) ? g_Xh : g_W1h;
    size_t t = (size_t)blockIdx.x * 256 + threadIdx.x;   // one float4 per thread
    float4 v = *((const float4*)src + t);
    __half2 h0 = __floats2half2_rn(v.x, v.y);
    __half2 h1 = __floats2half2_rn(v.z, v.w);
    *(uint2*)(dst + t * 4) = make_uint2(h2u(h0), h2u(h1));
}

// ---------------- W2 transpose + convert: [E,H,D] fp32 -> [E,D][H] fp16 ----------------
__global__ void conv_w2t(const float* __restrict__ w2) {
    __shared__ float tile[32][33];
    int e  = blockIdx.z;
    int d0 = blockIdx.x * 32;
    int h0 = blockIdx.y * 32;
    int tx = threadIdx.x, ty = threadIdx.y;
#pragma unroll
    for (int r = 0; r < 4; r++) {
        int h = h0 + ty + r * 8;
        tile[ty + r * 8][tx] = w2[((size_t)(e * H_ + h)) * D_ + d0 + tx];
    }
    __syncthreads();
#pragma unroll
    for (int r = 0; r < 4; r++) {
        int d = d0 + ty + r * 8;
        int h = h0 + tx;
        g_W2T[((size_t)(e * D_ + d)) * H_ + h] = __float2half_rn(tile[tx][ty + r * 8]);
    }
}

// ---------------- out += partial (after split-K GEMM2) ----------------
__global__ void add_partial(float* __restrict__ out) {
    size_t t = (size_t)blockIdx.x * 256 + threadIdx.x;   // one float4 per thread
    float4 o = ((const float4*)out)[t];
    float4 p = ((const float4*)g_P)[t];
    o.x += p.x; o.y += p.y; o.z += p.z; o.w += p.w;
    ((float4*)out)[t] = o;
}

// ---------------- fp16 GEMM via mma.sync (cp.async pipeline), R8 engine ----------------
// 128 threads, 4 warps (2x2 grid) of 64x64 warp tiles, 128x128 CTA tile,
// 3 smem stages (96 KB) -> 2 CTAs/SM.
// PHASE 1: KSL=1. relu(X W1^T + b1) -> g_Y (fp16)
// PHASE 2: KSL=2 split-K. slice 0: +b2 -> out ; slice 1: raw partial -> g_P
#define TM 128
#define TN 128
#define WM 64
#define WN 64
#define NSTAGE 3
#define STB ((TM + TN) * 128)              // 32 KB per stage
#define SMEM_TOT (NSTAGE * STB)            // 96 KB

template<int PHASE, int KSL>
__global__ void __launch_bounds__(128, 2) gemm_mma(const float* __restrict__ bias,
                                                   float* __restrict__ outF) {
    constexpr int Ntot = (PHASE == 1) ? H_ : D_;
    constexpr int KSEG = (PHASE == 1) ? D_ : H_;
    constexpr int KCTA = KSEG / KSL;       // K handled by one CTA
    constexpr int NCH  = KCTA / 64;        // 64-wide K chunks
    constexpr int Mt   = CAP_ / TM;
    constexpr int Nt   = Ntot / TN;
    constexpr int TILES = Mt * Nt * E_;
    constexpr int WROWS = WM / 16, WCOLS = WN / 8, BT16 = WN / 16;

    extern __shared__ char smem[];
    const uint32_t sb = smem_u32(smem);
    const int tid = threadIdx.x, wid = tid >> 5, lane = tid & 31;

    const int ks  = blockIdx.x / TILES;    // k-slice (0 for PHASE 1)
    const int idx = blockIdx.x % TILES;
    const int mt = idx % Mt;
    const int nt = (idx / Mt) % Nt;
    const int e  = idx / (Mt * Nt);
    const int m0 = mt * TM, n0 = nt * TN;
    const int kbase = ks * KCTA;

    const __half* A = (PHASE == 1) ? g_Xh  : g_Y;
    const __half* B = (PHASE == 1) ? g_W1h : g_W2T;
    const __half* Ab = A + (size_t)(e * CAP_ + m0) * KSEG + kbase;
    const __half* Bb = B + (size_t)(e * Ntot + n0) * KSEG + kbase;

    auto issue = [&](int c) {
        const int k0 = c * 64;
        const int st = c % NSTAGE;
        const uint32_t sA = sb + st * STB, sB = sA + TM * 128;
#pragma unroll
        for (int t = 0; t < TM / 16; t++) {            // A: TM*8 chunks / 128 thr
            int i = t * 128 + tid, row = i >> 3, c16 = i & 7;
            cpa16(sA + row * 128 + ((c16 ^ (row & 7)) << 4),
                  Ab + (size_t)row * KSEG + k0 + c16 * 8);
        }
#pragma unroll
        for (int t = 0; t < TN / 16; t++) {            // B: TN*8 chunks / 128 thr
            int i = t * 128 + tid, row = i >> 3, c16 = i & 7;
            cpa16(sB + row * 128 + ((c16 ^ (row & 7)) << 4),
                  Bb + (size_t)row * KSEG + k0 + c16 * 8);
        }
        asm volatile("cp.async.commit_group;" ::: "memory");
    };

    const int m_off = (wid >> 1) * WM;     // 2x2 warp grid
    const int n_off = (wid & 1) * WN;
    float acc[WROWS][WCOLS][4] = {};

    issue(0);
    issue(1);
    asm volatile("cp.async.wait_group 1;" ::: "memory");
    __syncthreads();

    for (int c = 0; c < NCH; ++c) {
        const int st = c % NSTAGE;
        const uint32_t sA = sb + st * STB, sB = sA + TM * 128;
#pragma unroll
        for (int kk = 0; kk < 4; ++kk) {               // 4 x k16 per 64-chunk
            uint32_t aF[WROWS][4];
#pragma unroll
            for (int i = 0; i < WROWS; ++i) {
                int row = m_off + 16 * i + (lane & 15);
                int ch  = kk * 2 + (lane >> 4);
                ldsm4(aF[i], sA + row * 128 + ((ch ^ (row & 7)) << 4));
            }
            uint32_t bF[BT16][4];
#pragma unroll
            for (int j4 = 0; j4 < BT16; ++j4) {
                int row = n_off + 16 * j4 + ((lane >> 4) << 3) + (lane & 7);
                int ch  = kk * 2 + ((lane >> 3) & 1);
                ldsm4(bF[j4], sB + row * 128 + ((ch ^ (row & 7)) << 4));
            }
#pragma unroll
            for (int i = 0; i < WROWS; ++i)
#pragma unroll
                for (int j = 0; j < WCOLS; ++j)
                    mma16816(acc[i][j], aF[i], bF[j >> 1][(j & 1) * 2], bF[j >> 1][(j & 1) * 2 + 1]);
        }
        if (c + 2 < NCH) issue(c + 2);
        else asm volatile("cp.async.commit_group;" ::: "memory");
        asm volatile("cp.async.wait_group 1;" ::: "memory");
        __syncthreads();
    }

    // ---- epilogue ----
    const int r_lane = lane >> 2;
    const int c_lane = (lane & 3) * 2;
    const float* brow = bias + (size_t)e * Ntot;
#pragma unroll
    for (int i = 0; i < WROWS; ++i) {
#pragma unroll
        for (int half = 0; half < 2; ++half) {
            const int m = m0 + m_off + 16 * i + r_lane + half * 8;
            if (PHASE == 1) {
                __half* yrow = g_Y + (size_t)(e * CAP_ + m) * H_;
#pragma unroll
                for (int j = 0; j < WCOLS; ++j) {
                    const int col = n0 + n_off + 8 * j + c_lane;
                    float v0 = acc[i][j][half * 2 + 0] + brow[col];
                    float v1 = acc[i][j][half * 2 + 1] + brow[col + 1];
                    v0 = fmaxf(v0, 0.f);
                    v1 = fmaxf(v1, 0.f);
                    *(uint32_t*)(yrow + col) = h2u(__floats2half2_rn(v0, v1));
                }
            } else {
                // slice 0: out = acc + bias ; slice 1: g_P = acc (raw partial)
                float* obase = (ks == 0) ? outF : g_P;
                float* orow = obase + (size_t)(e * CAP_ + m) * D_;
#pragma unroll
                for (int j = 0; j < WCOLS; ++j) {
                    const int col = n0 + n_off + 8 * j + c_lane;
                    const float b0v = (ks == 0) ? brow[col]     : 0.f;
                    const float b1v = (ks == 0) ? brow[col + 1] : 0.f;
                    float2 f;
                    f.x = acc[i][j][half * 2 + 0] + b0v;
                    f.y = acc[i][j][half * 2 + 1] + b1v;
                    *(float2*)(orow + col) = f;
                }
            }
        }
    }
}

// ---------------- launch ----------------
extern "C" void kernel_launch(void* const* d_in, const int* in_sizes, int n_in,
                              void* d_out, int out_size) {
    const float* x  = (const float*)d_in[0];   // [E, CAP, D]
    const float* w1 = (const float*)d_in[1];   // [E, H, D]
    const float* b1 = (const float*)d_in[2];   // [E, H]
    const float* w2 = (const float*)d_in[3];   // [E, H, D]
    const float* b2 = (const float*)d_in[4];   // [E, D]
    float* out = (float*)d_out;                // [E, CAP, D]

    auto g1 = gemm_mma<1, 1>;                  // GEMM1: no split
    auto g2 = gemm_mma<2, 2>;                  // GEMM2: split-K=2

    cudaFuncSetAttribute(g1, cudaFuncAttributeMaxDynamicSharedMemorySize, SMEM_TOT);
    cudaFuncSetAttribute(g2, cudaFuncAttributeMaxDynamicSharedMemorySize, SMEM_TOT);

    // 1) conversions (destinations resolved in device code)
    conv_f16<0><<<(E_ * CAP_ * D_ / 4) / 256, 256>>>(x);           // X  -> g_Xh
    conv_f16<1><<<(E_ * H_   * D_ / 4) / 256, 256>>>(w1);          // W1 -> g_W1h
    conv_w2t<<<dim3(D_ / 32, H_ / 32, E_), dim3(32, 8)>>>(w2);     // W2 -> g_W2T (transposed)

    // 2) GEMM1: relu(X W1^T + b1) -> g_Y (fp16)
    g1<<<(CAP_ / TM) * (H_ / TN) * E_, 128, SMEM_TOT>>>(b1, nullptr);

    // 3) GEMM2 split-K=2: slice0 -> out (+b2), slice1 -> g_P
    g2<<<(CAP_ / TM) * (D_ / TN) * E_ * 2, 128, SMEM_TOT>>>(b2, out);

    // 4) out += g_P
    add_partial<<<(E_ * CAP_ * D_ / 4) / 256, 256>>>(out);
}

// round 12
// speedup vs baseline: 1.0479x; 1.0433x over previous
#include <cuda_runtime.h>
#include <cuda_fp16.h>
#include <cstdint>

#define E_   8
#define CAP_ 2048
#define D_   1024
#define H_   4096

// ---------------- scratch (device globals; no runtime allocation) ----------------
__device__ __half g_Xh [(size_t)E_ * CAP_ * D_];   // [E*2048][1024]
__device__ __half g_W1h[(size_t)E_ * H_   * D_];   // [E*4096][1024]
__device__ __half g_W2T[(size_t)E_ * D_   * H_];   // [E*1024][4096]  (W2^T)
__device__ __half g_Y  [(size_t)E_ * CAP_ * H_];   // [E*2048][4096]

// ---------------- PTX helpers (portable: sm_80+ features only) ----------------
__device__ __forceinline__ uint32_t smem_u32(const void* p) {
    uint32_t a;
    asm("{ .reg .u64 t; cvta.to.shared.u64 t, %1; cvt.u32.u64 %0, t; }" : "=r"(a) : "l"(p));
    return a;
}
__device__ __forceinline__ void cpa16(uint32_t s, const void* g) {
    asm volatile("cp.async.cg.shared.global [%0], [%1], 16;" :: "r"(s), "l"(g) : "memory");
}
__device__ __forceinline__ void ldsm4(uint32_t r[4], uint32_t addr) {
    asm volatile("ldmatrix.sync.aligned.m8n8.x4.shared.b16 {%0,%1,%2,%3}, [%4];"
                 : "=r"(r[0]), "=r"(r[1]), "=r"(r[2]), "=r"(r[3]) : "r"(addr));
}
__device__ __forceinline__ void mma16816(float d[4], const uint32_t a[4],
                                         uint32_t b0, uint32_t b1) {
    asm volatile("mma.sync.aligned.m16n8k16.row.col.f32.f16.f16.f32 "
                 "{%0,%1,%2,%3},{%4,%5,%6,%7},{%8,%9},{%0,%1,%2,%3};"
                 : "+f"(d[0]), "+f"(d[1]), "+f"(d[2]), "+f"(d[3])
                 : "r"(a[0]), "r"(a[1]), "r"(a[2]), "r"(a[3]), "r"(b0), "r"(b1));
}
__device__ __forceinline__ uint32_t h2u(__half2 h) {
    return *reinterpret_cast<uint32_t*>(&h);
}

// ---------------- convert: fp32 -> fp16 elementwise; dst chosen in DEVICE code ----------------
template<int TGT>   // 0 -> g_Xh, 1 -> g_W1h
__global__ void conv_f16(const float* __restrict__ src) {
    __half* dst = (TGT == 0) ? g_Xh : g_W1h;
    size_t t = (size_t)blockIdx.x * 256 + threadIdx.x;   // one float4 per thread
    float4 v = *((const float4*)src + t);
    __half2 h0 = __floats2half2_rn(v.x, v.y);
    __half2 h1 = __floats2half2_rn(v.z, v.w);
    *(uint2*)(dst + t * 4) = make_uint2(h2u(h0), h2u(h1));
}

// ---------------- W2 transpose + convert: [E,H,D] fp32 -> [E,D][H] fp16 ----------------
__global__ void conv_w2t(const float* __restrict__ w2) {
    __shared__ float tile[32][33];
    int e  = blockIdx.z;
    int d0 = blockIdx.x * 32;
    int h0 = blockIdx.y * 32;
    int tx = threadIdx.x, ty = threadIdx.y;
#pragma unroll
    for (int r = 0; r < 4; r++) {
        int h = h0 + ty + r * 8;
        tile[ty + r * 8][tx] = w2[((size_t)(e * H_ + h)) * D_ + d0 + tx];
    }
    __syncthreads();
#pragma unroll
    for (int r = 0; r < 4; r++) {
        int d = d0 + ty + r * 8;
        int h = h0 + tx;
        g_W2T[((size_t)(e * D_ + d)) * H_ + h] = __float2half_rn(tile[tx][ty + r * 8]);
    }
}

// ---------------- fp16 GEMM via mma.sync (cp.async pipeline), R8 engine ----------------
// 128x128 CTA tile, 4 warps (2x2) of 64x64 warp tiles, 128 threads,
// 3 stages (96 KB smem) -> 2 CTAs/SM.
#define TM 128
#define TN 128
#define WM 64
#define WN 64
#define NSTAGE 3
#define STB ((TM + TN) * 128)              // 32 KB per stage
#define SMEM_TOT (NSTAGE * STB)            // 96 KB

template<int PHASE>
__global__ void __launch_bounds__(128, 2) gemm_mma(const float* __restrict__ bias,
                                                   float* __restrict__ outF) {
    constexpr int Ntot = (PHASE == 1) ? H_ : D_;
    constexpr int KSEG = (PHASE == 1) ? D_ : H_;
    constexpr int NCH  = KSEG / 64;        // 64-wide K chunks
    constexpr int Mt   = CAP_ / TM;
    constexpr int Nt   = Ntot / TN;
    constexpr int WROWS = WM / 16, WCOLS = WN / 8, BT16 = WN / 16;

    extern __shared__ char smem[];
    const uint32_t sb = smem_u32(smem);
    const int tid = threadIdx.x, wid = tid >> 5, lane = tid & 31;

    const int idx = blockIdx.x;
    const int mt = idx % Mt;
    const int nt = (idx / Mt) % Nt;
    const int e  = idx / (Mt * Nt);
    const int m0 = mt * TM, n0 = nt * TN;

    const __half* A = (PHASE == 1) ? g_Xh  : g_Y;
    const __half* B = (PHASE == 1) ? g_W1h : g_W2T;
    const __half* Ab = A + (size_t)(e * CAP_ + m0) * KSEG;
    const __half* Bb = B + (size_t)(e * Ntot + n0) * KSEG;

    auto issue = [&](int c) {
        const int k0 = c * 64;
        const int st = c % NSTAGE;
        const uint32_t sA = sb + st * STB, sB = sA + TM * 128;
#pragma unroll
        for (int t = 0; t < TM / 16; t++) {            // A: TM*8 chunks / 128 thr
            int i = t * 128 + tid, row = i >> 3, c16 = i & 7;
            cpa16(sA + row * 128 + ((c16 ^ (row & 7)) << 4),
                  Ab + (size_t)row * KSEG + k0 + c16 * 8);
        }
#pragma unroll
        for (int t = 0; t < TN / 16; t++) {            // B: TN*8 chunks / 128 thr
            int i = t * 128 + tid, row = i >> 3, c16 = i & 7;
            cpa16(sB + row * 128 + ((c16 ^ (row & 7)) << 4),
                  Bb + (size_t)row * KSEG + k0 + c16 * 8);
        }
        asm volatile("cp.async.commit_group;" ::: "memory");
    };

    const int m_off = (wid >> 1) * WM;     // 2x2 warp grid
    const int n_off = (wid & 1) * WN;
    float acc[WROWS][WCOLS][4] = {};

    issue(0);
    issue(1);
    asm volatile("cp.async.wait_group 1;" ::: "memory");
    __syncthreads();

    for (int c = 0; c < NCH; ++c) {
        const int st = c % NSTAGE;
        const uint32_t sA = sb + st * STB, sB = sA + TM * 128;
#pragma unroll
        for (int kk = 0; kk < 4; ++kk) {               // 4 x k16 per 64-chunk
            uint32_t aF[WROWS][4];
#pragma unroll
            for (int i = 0; i < WROWS; ++i) {
                int row = m_off + 16 * i + (lane & 15);
                int ch  = kk * 2 + (lane >> 4);
                ldsm4(aF[i], sA + row * 128 + ((ch ^ (row & 7)) << 4));
            }
            uint32_t bF[BT16][4];
#pragma unroll
            for (int j4 = 0; j4 < BT16; ++j4) {
                int row = n_off + 16 * j4 + ((lane >> 4) << 3) + (lane & 7);
                int ch  = kk * 2 + ((lane >> 3) & 1);
                ldsm4(bF[j4], sB + row * 128 + ((ch ^ (row & 7)) << 4));
            }
#pragma unroll
            for (int i = 0; i < WROWS; ++i)
#pragma unroll
                for (int j = 0; j < WCOLS; ++j)
                    mma16816(acc[i][j], aF[i], bF[j >> 1][(j & 1) * 2], bF[j >> 1][(j & 1) * 2 + 1]);
        }
        if (c + 2 < NCH) issue(c + 2);
        else asm volatile("cp.async.commit_group;" ::: "memory");
        asm volatile("cp.async.wait_group 1;" ::: "memory");
        __syncthreads();
    }

    // ---- epilogue ----
    const int r_lane = lane >> 2;
    const int c_lane = (lane & 3) * 2;
    const float* brow = bias + (size_t)e * Ntot;
#pragma unroll
    for (int i = 0; i < WROWS; ++i) {
#pragma unroll
        for (int half = 0; half < 2; ++half) {
            const int m = m0 + m_off + 16 * i + r_lane + half * 8;
            if (PHASE == 1) {
                __half* yrow = g_Y + (size_t)(e * CAP_ + m) * H_;
#pragma unroll
                for (int j = 0; j < WCOLS; ++j) {
                    const int col = n0 + n_off + 8 * j + c_lane;
                    float v0 = acc[i][j][half * 2 + 0] + brow[col];
                    float v1 = acc[i][j][half * 2 + 1] + brow[col + 1];
                    v0 = fmaxf(v0, 0.f);
                    v1 = fmaxf(v1, 0.f);
                    *(uint32_t*)(yrow + col) = h2u(__floats2half2_rn(v0, v1));
                }
            } else {
                float* orow = outF + (size_t)(e * CAP_ + m) * D_;
#pragma unroll
                for (int j = 0; j < WCOLS; ++j) {
                    const int col = n0 + n_off + 8 * j + c_lane;
                    float2 f;
                    f.x = acc[i][j][half * 2 + 0] + brow[col];
                    f.y = acc[i][j][half * 2 + 1] + brow[col + 1];
                    *(float2*)(orow + col) = f;
                }
            }
        }
    }
}

// ---------------- launch ----------------
extern "C" void kernel_launch(void* const* d_in, const int* in_sizes, int n_in,
                              void* d_out, int out_size) {
    const float* x  = (const float*)d_in[0];   // [E, CAP, D]
    const float* w1 = (const float*)d_in[1];   // [E, H, D]
    const float* b1 = (const float*)d_in[2];   // [E, H]
    const float* w2 = (const float*)d_in[3];   // [E, H, D]
    const float* b2 = (const float*)d_in[4];   // [E, D]
    float* out = (float*)d_out;                // [E, CAP, D]

    // One-time side-stream + events (resource init only; identical work every call;
    // no device memory allocation).
    static cudaStream_t s_side = nullptr;
    static cudaEvent_t  ev_fork = nullptr, ev_join = nullptr;
    if (s_side == nullptr) {
        cudaStreamCreateWithFlags(&s_side, cudaStreamNonBlocking);
        cudaEventCreateWithFlags(&ev_fork, cudaEventDisableTiming);
        cudaEventCreateWithFlags(&ev_join, cudaEventDisableTiming);
    }

    cudaFuncSetAttribute(gemm_mma<1>, cudaFuncAttributeMaxDynamicSharedMemorySize, SMEM_TOT);
    cudaFuncSetAttribute(gemm_mma<2>, cudaFuncAttributeMaxDynamicSharedMemorySize, SMEM_TOT);

    // Fork: conv_w2t runs on the side stream, concurrent with conv_x/conv_w1/GEMM1
    // (GEMM1 is tensor-bound with ~94% of DRAM bandwidth idle).
    cudaEventRecord(ev_fork, 0);
    cudaStreamWaitEvent(s_side, ev_fork, 0);
    conv_w2t<<<dim3(D_ / 32, H_ / 32, E_), dim3(32, 8), 0, s_side>>>(w2);  // W2 -> g_W2T
    cudaEventRecord(ev_join, s_side);

    // Main stream: X/W1 conversions, then GEMM1.
    conv_f16<0><<<(E_ * CAP_ * D_ / 4) / 256, 256>>>(x);           // X  -> g_Xh
    conv_f16<1><<<(E_ * H_   * D_ / 4) / 256, 256>>>(w1);          // W1 -> g_W1h
    gemm_mma<1><<<(CAP_ / TM) * (H_ / TN) * E_, 128, SMEM_TOT>>>(b1, nullptr);

    // Join: GEMM2 needs both GEMM1 (stream order) and conv_w2t (event).
    cudaStreamWaitEvent(0, ev_join, 0);
    gemm_mma<2><<<(CAP_ / TM) * (D_ / TN) * E_, 128, SMEM_TOT>>>(b2, out);
}

// round 13
// speedup vs baseline: 1.0625x; 1.0139x over previous
#include <cuda_runtime.h>
#include <cuda_fp16.h>
#include <cstdint>

#define E_   8
#define CAP_ 2048
#define D_   1024
#define H_   4096

// ---------------- scratch (device globals; no runtime allocation) ----------------
__device__ __half g_Xh [(size_t)E_ * CAP_ * D_];   // [E*2048][1024]
__device__ __half g_W1h[(size_t)E_ * H_   * D_];   // [E*4096][1024]
__device__ __half g_W2T[(size_t)E_ * D_   * H_];   // [E*1024][4096]  (W2^T)
__device__ __half g_Y  [(size_t)E_ * CAP_ * H_];   // [E*2048][4096]

// ---------------- PTX helpers (portable: sm_80+ features only) ----------------
__device__ __forceinline__ uint32_t smem_u32(const void* p) {
    uint32_t a;
    asm("{ .reg .u64 t; cvta.to.shared.u64 t, %1; cvt.u32.u64 %0, t; }" : "=r"(a) : "l"(p));
    return a;
}
__device__ __forceinline__ void cpa16(uint32_t s, const void* g) {
    asm volatile("cp.async.cg.shared.global [%0], [%1], 16;" :: "r"(s), "l"(g) : "memory");
}
__device__ __forceinline__ void ldsm4(uint32_t r[4], uint32_t addr) {
    asm volatile("ldmatrix.sync.aligned.m8n8.x4.shared.b16 {%0,%1,%2,%3}, [%4];"
                 : "=r"(r[0]), "=r"(r[1]), "=r"(r[2]), "=r"(r[3]) : "r"(addr));
}
__device__ __forceinline__ void mma16816(float d[4], const uint32_t a[4],
                                         uint32_t b0, uint32_t b1) {
    asm volatile("mma.sync.aligned.m16n8k16.row.col.f32.f16.f16.f32 "
                 "{%0,%1,%2,%3},{%4,%5,%6,%7},{%8,%9},{%0,%1,%2,%3};"
                 : "+f"(d[0]), "+f"(d[1]), "+f"(d[2]), "+f"(d[3])
                 : "r"(a[0]), "r"(a[1]), "r"(a[2]), "r"(a[3]), "r"(b0), "r"(b1));
}
__device__ __forceinline__ uint32_t h2u(__half2 h) {
    return *reinterpret_cast<uint32_t*>(&h);
}

// ---------------- convert: fp32 -> fp16 elementwise; dst chosen in DEVICE code ----------------
template<int TGT>   // 0 -> g_Xh, 1 -> g_W1h
__global__ void conv_f16(const float* __restrict__ src) {
    __half* dst = (TGT == 0) ? g_Xh : g_W1h;
    size_t t = (size_t)blockIdx.x * 256 + threadIdx.x;   // one float4 per thread
    float4 v = *((const float4*)src + t);
    __half2 h0 = __floats2half2_rn(v.x, v.y);
    __half2 h1 = __floats2half2_rn(v.z, v.w);
    *(uint2*)(dst + t * 4) = make_uint2(h2u(h0), h2u(h1));
}

// ---------------- W2 transpose + convert, 64-thread blocks ----------------
// Small blocks (64 thr, ~2K regs) so one CTA co-resides with 2 GEMM CTAs
// (61.7K regs) inside the 64K RF/SM — lets it execute DURING GEMM1.
__global__ void __launch_bounds__(64) conv_w2t(const float* __restrict__ w2) {
    __shared__ float tile[32][33];
    int e  = blockIdx.z;
    int d0 = blockIdx.x * 32;
    int h0 = blockIdx.y * 32;
    int tx = threadIdx.x, ty = threadIdx.y;              // (32, 2)
#pragma unroll
    for (int r = 0; r < 16; r++) {
        int h = h0 + ty + r * 2;
        tile[ty + r * 2][tx] = w2[((size_t)(e * H_ + h)) * D_ + d0 + tx];
    }
    __syncthreads();
#pragma unroll
    for (int r = 0; r < 16; r++) {
        int d = d0 + ty + r * 2;
        int h = h0 + tx;
        g_W2T[((size_t)(e * D_ + d)) * H_ + h] = __float2half_rn(tile[tx][ty + r * 2]);
    }
}

// ---------------- fp16 GEMM via mma.sync (cp.async pipeline), R8 engine ----------------
// 128x128 CTA tile, 4 warps (2x2) of 64x64 warp tiles, 128 threads,
// 3 stages (96 KB smem) -> 2 CTAs/SM.
#define TM 128
#define TN 128
#define WM 64
#define WN 64
#define NSTAGE 3
#define STB ((TM + TN) * 128)              // 32 KB per stage
#define SMEM_TOT (NSTAGE * STB)            // 96 KB

template<int PHASE>
__global__ void __launch_bounds__(128, 2) gemm_mma(const float* __restrict__ bias,
                                                   float* __restrict__ outF) {
    constexpr int Ntot = (PHASE == 1) ? H_ : D_;
    constexpr int KSEG = (PHASE == 1) ? D_ : H_;
    constexpr int NCH  = KSEG / 64;        // 64-wide K chunks
    constexpr int Mt   = CAP_ / TM;
    constexpr int Nt   = Ntot / TN;
    constexpr int WROWS = WM / 16, WCOLS = WN / 8, BT16 = WN / 16;

    extern __shared__ char smem[];
    const uint32_t sb = smem_u32(smem);
    const int tid = threadIdx.x, wid = tid >> 5, lane = tid & 31;

    const int idx = blockIdx.x;
    const int mt = idx % Mt;
    const int nt = (idx / Mt) % Nt;
    const int e  = idx / (Mt * Nt);
    const int m0 = mt * TM, n0 = nt * TN;

    const __half* A = (PHASE == 1) ? g_Xh  : g_Y;
    const __half* B = (PHASE == 1) ? g_W1h : g_W2T;
    const __half* Ab = A + (size_t)(e * CAP_ + m0) * KSEG;
    const __half* Bb = B + (size_t)(e * Ntot + n0) * KSEG;

    auto issue = [&](int c) {
        const int k0 = c * 64;
        const int st = c % NSTAGE;
        const uint32_t sA = sb + st * STB, sB = sA + TM * 128;
#pragma unroll
        for (int t = 0; t < TM / 16; t++) {            // A: TM*8 chunks / 128 thr
            int i = t * 128 + tid, row = i >> 3, c16 = i & 7;
            cpa16(sA + row * 128 + ((c16 ^ (row & 7)) << 4),
                  Ab + (size_t)row * KSEG + k0 + c16 * 8);
        }
#pragma unroll
        for (int t = 0; t < TN / 16; t++) {            // B: TN*8 chunks / 128 thr
            int i = t * 128 + tid, row = i >> 3, c16 = i & 7;
            cpa16(sB + row * 128 + ((c16 ^ (row & 7)) << 4),
                  Bb + (size_t)row * KSEG + k0 + c16 * 8);
        }
        asm volatile("cp.async.commit_group;" ::: "memory");
    };

    const int m_off = (wid >> 1) * WM;     // 2x2 warp grid
    const int n_off = (wid & 1) * WN;
    float acc[WROWS][WCOLS][4] = {};

    issue(0);
    issue(1);
    asm volatile("cp.async.wait_group 1;" ::: "memory");
    __syncthreads();

    for (int c = 0; c < NCH; ++c) {
        const int st = c % NSTAGE;
        const uint32_t sA = sb + st * STB, sB = sA + TM * 128;
#pragma unroll
        for (int kk = 0; kk < 4; ++kk) {               // 4 x k16 per 64-chunk
            uint32_t aF[WROWS][4];
#pragma unroll
            for (int i = 0; i < WROWS; ++i) {
                int row = m_off + 16 * i + (lane & 15);
                int ch  = kk * 2 + (lane >> 4);
                ldsm4(aF[i], sA + row * 128 + ((ch ^ (row & 7)) << 4));
            }
            uint32_t bF[BT16][4];
#pragma unroll
            for (int j4 = 0; j4 < BT16; ++j4) {
                int row = n_off + 16 * j4 + ((lane >> 4) << 3) + (lane & 7);
                int ch  = kk * 2 + ((lane >> 3) & 1);
                ldsm4(bF[j4], sB + row * 128 + ((ch ^ (row & 7)) << 4));
            }
#pragma unroll
            for (int i = 0; i < WROWS; ++i)
#pragma unroll
                for (int j = 0; j < WCOLS; ++j)
                    mma16816(acc[i][j], aF[i], bF[j >> 1][(j & 1) * 2], bF[j >> 1][(j & 1) * 2 + 1]);
        }
        if (c + 2 < NCH) issue(c + 2);
        else asm volatile("cp.async.commit_group;" ::: "memory");
        asm volatile("cp.async.wait_group 1;" ::: "memory");
        __syncthreads();
    }

    // ---- epilogue ----
    const int r_lane = lane >> 2;
    const int c_lane = (lane & 3) * 2;
    const float* brow = bias + (size_t)e * Ntot;
#pragma unroll
    for (int i = 0; i < WROWS; ++i) {
#pragma unroll
        for (int half = 0; half < 2; ++half) {
            const int m = m0 + m_off + 16 * i + r_lane + half * 8;
            if (PHASE == 1) {
                __half* yrow = g_Y + (size_t)(e * CAP_ + m) * H_;
#pragma unroll
                for (int j = 0; j < WCOLS; ++j) {
                    const int col = n0 + n_off + 8 * j + c_lane;
                    float v0 = acc[i][j][half * 2 + 0] + brow[col];
                    float v1 = acc[i][j][half * 2 + 1] + brow[col + 1];
                    v0 = fmaxf(v0, 0.f);
                    v1 = fmaxf(v1, 0.f);
                    *(uint32_t*)(yrow + col) = h2u(__floats2half2_rn(v0, v1));
                }
            } else {
                float* orow = outF + (size_t)(e * CAP_ + m) * D_;
#pragma unroll
                for (int j = 0; j < WCOLS; ++j) {
                    const int col = n0 + n_off + 8 * j + c_lane;
                    float2 f;
                    f.x = acc[i][j][half * 2 + 0] + brow[col];
                    f.y = acc[i][j][half * 2 + 1] + brow[col + 1];
                    *(float2*)(orow + col) = f;
                }
            }
        }
    }
}

// ---------------- launch ----------------
extern "C" void kernel_launch(void* const* d_in, const int* in_sizes, int n_in,
                              void* d_out, int out_size) {
    const float* x  = (const float*)d_in[0];   // [E, CAP, D]
    const float* w1 = (const float*)d_in[1];   // [E, H, D]
    const float* b1 = (const float*)d_in[2];   // [E, H]
    const float* w2 = (const float*)d_in[3];   // [E, H, D]
    const float* b2 = (const float*)d_in[4];   // [E, D]
    float* out = (float*)d_out;                // [E, CAP, D]

    // One-time side-stream + events (resource init only; no device memory).
    static cudaStream_t s_side = nullptr;
    static cudaEvent_t  ev_fork = nullptr, ev_join = nullptr;
    if (s_side == nullptr) {
        cudaStreamCreateWithFlags(&s_side, cudaStreamNonBlocking);
        cudaEventCreateWithFlags(&ev_fork, cudaEventDisableTiming);
        cudaEventCreateWithFlags(&ev_join, cudaEventDisableTiming);
    }

    cudaFuncSetAttribute(gemm_mma<1>, cudaFuncAttributeMaxDynamicSharedMemorySize, SMEM_TOT);
    cudaFuncSetAttribute(gemm_mma<2>, cudaFuncAttributeMaxDynamicSharedMemorySize, SMEM_TOT);

    // X/W1 conversions (DRAM-bound; GEMM1 depends on them).
    conv_f16<0><<<(E_ * CAP_ * D_ / 4) / 256, 256>>>(x);           // X  -> g_Xh
    conv_f16<1><<<(E_ * H_   * D_ / 4) / 256, 256>>>(w1);          // W1 -> g_W1h

    // Fork AFTER conv_w1: conv_w2t becomes ready exactly when GEMM1 does,
    // so it executes DURING GEMM1 (DRAM 6% busy, RF slack fits 64-thr CTAs),
    // not alongside the other (bandwidth-bound) conversions.
    cudaEventRecord(ev_fork, 0);
    cudaStreamWaitEvent(s_side, ev_fork, 0);
    conv_w2t<<<dim3(D_ / 32, H_ / 32, E_), dim3(32, 2), 0, s_side>>>(w2);  // W2 -> g_W2T
    cudaEventRecord(ev_join, s_side);

    // GEMM1: relu(X W1^T + b1) -> g_Y (fp16)
    gemm_mma<1><<<(CAP_ / TM) * (H_ / TN) * E_, 128, SMEM_TOT>>>(b1, nullptr);

    // Join: GEMM2 needs GEMM1 (stream order) + conv_w2t (event).
    cudaStreamWaitEvent(0, ev_join, 0);
    gemm_mma<2><<<(CAP_ / TM) * (D_ / TN) * E_, 128, SMEM_TOT>>>(b2, out);
}

// round 14
// speedup vs baseline: 1.0655x; 1.0028x over previous
#include <cuda_runtime.h>
#include <cuda_fp16.h>
#include <cstdint>

#define E_   8
#define CAP_ 2048
#define D_   1024
#define H_   4096

// ---------------- scratch (device globals; no runtime allocation) ----------------
__device__ __half g_Xh [(size_t)E_ * CAP_ * D_];   // [E*2048][1024]
__device__ __half g_W1h[(size_t)E_ * H_   * D_];   // [E*4096][1024]
__device__ __half g_W2T[(size_t)E_ * D_   * H_];   // [E*1024][4096]  (W2^T)
__device__ __half g_Y  [(size_t)E_ * CAP_ * H_];   // [E*2048][4096]

// ---------------- PTX helpers (portable: sm_80+ features only) ----------------
__device__ __forceinline__ uint32_t smem_u32(const void* p) {
    uint32_t a;
    asm("{ .reg .u64 t; cvta.to.shared.u64 t, %1; cvt.u32.u64 %0, t; }" : "=r"(a) : "l"(p));
    return a;
}
__device__ __forceinline__ void cpa16(uint32_t s, const void* g) {
    asm volatile("cp.async.cg.shared.global [%0], [%1], 16;" :: "r"(s), "l"(g) : "memory");
}
__device__ __forceinline__ void ldsm4(uint32_t r[4], uint32_t addr) {
    asm volatile("ldmatrix.sync.aligned.m8n8.x4.shared.b16 {%0,%1,%2,%3}, [%4];"
                 : "=r"(r[0]), "=r"(r[1]), "=r"(r[2]), "=r"(r[3]) : "r"(addr));
}
__device__ __forceinline__ void mma16816(float d[4], const uint32_t a[4],
                                         uint32_t b0, uint32_t b1) {
    asm volatile("mma.sync.aligned.m16n8k16.row.col.f32.f16.f16.f32 "
                 "{%0,%1,%2,%3},{%4,%5,%6,%7},{%8,%9},{%0,%1,%2,%3};"
                 : "+f"(d[0]), "+f"(d[1]), "+f"(d[2]), "+f"(d[3])
                 : "r"(a[0]), "r"(a[1]), "r"(a[2]), "r"(a[3]), "r"(b0), "r"(b1));
}
__device__ __forceinline__ uint32_t h2u(__half2 h) {
    return *reinterpret_cast<uint32_t*>(&h);
}

// ---------------- convert: fp32 -> fp16 elementwise, element-offset variant ----------
// dst symbol chosen in DEVICE code; dstoff is a plain element offset (host-computed
// number, no host reference to the __device__ symbol).
template<int TGT>   // 0 -> g_Xh, 1 -> g_W1h
__global__ void conv_f16(const float* __restrict__ src, size_t dstoff) {
    __half* dst = ((TGT == 0) ? g_Xh : g_W1h) + dstoff;
    size_t t = (size_t)blockIdx.x * 256 + threadIdx.x;   // one float4 per thread
    float4 v = *((const float4*)src + t);
    __half2 h0 = __floats2half2_rn(v.x, v.y);
    __half2 h1 = __floats2half2_rn(v.z, v.w);
    *(uint2*)(dst + t * 4) = make_uint2(h2u(h0), h2u(h1));
}

// ---------------- W2 transpose + convert, 64-thread blocks (runs hidden on side) ----
__global__ void __launch_bounds__(64) conv_w2t(const float* __restrict__ w2) {
    __shared__ float tile[32][33];
    int e  = blockIdx.z;
    int d0 = blockIdx.x * 32;
    int h0 = blockIdx.y * 32;
    int tx = threadIdx.x, ty = threadIdx.y;              // (32, 2)
#pragma unroll
    for (int r = 0; r < 16; r++) {
        int h = h0 + ty + r * 2;
        tile[ty + r * 2][tx] = w2[((size_t)(e * H_ + h)) * D_ + d0 + tx];
    }
    __syncthreads();
#pragma unroll
    for (int r = 0; r < 16; r++) {
        int d = d0 + ty + r * 2;
        int h = h0 + tx;
        g_W2T[((size_t)(e * D_ + d)) * H_ + h] = __float2half_rn(tile[tx][ty + r * 2]);
    }
}

// ---------------- fp16 GEMM via mma.sync (cp.async pipeline), R8 engine ----------------
// 128x128 CTA tile, 4 warps (2x2) of 64x64 warp tiles, 128 threads,
// 3 stages (96 KB smem) -> 2 CTAs/SM.  `ebase` = first expert of this launch.
#define TM 128
#define TN 128
#define WM 64
#define WN 64
#define NSTAGE 3
#define STB ((TM + TN) * 128)              // 32 KB per stage
#define SMEM_TOT (NSTAGE * STB)            // 96 KB

template<int PHASE>
__global__ void __launch_bounds__(128, 2) gemm_mma(const float* __restrict__ bias,
                                                   float* __restrict__ outF,
                                                   int ebase) {
    constexpr int Ntot = (PHASE == 1) ? H_ : D_;
    constexpr int KSEG = (PHASE == 1) ? D_ : H_;
    constexpr int NCH  = KSEG / 64;        // 64-wide K chunks
    constexpr int Mt   = CAP_ / TM;
    constexpr int Nt   = Ntot / TN;
    constexpr int WROWS = WM / 16, WCOLS = WN / 8, BT16 = WN / 16;

    extern __shared__ char smem[];
    const uint32_t sb = smem_u32(smem);
    const int tid = threadIdx.x, wid = tid >> 5, lane = tid & 31;

    const int idx = blockIdx.x;
    const int mt = idx % Mt;
    const int nt = (idx / Mt) % Nt;
    const int e  = ebase + idx / (Mt * Nt);
    const int m0 = mt * TM, n0 = nt * TN;

    const __half* A = (PHASE == 1) ? g_Xh  : g_Y;
    const __half* B = (PHASE == 1) ? g_W1h : g_W2T;
    const __half* Ab = A + (size_t)(e * CAP_ + m0) * KSEG;
    const __half* Bb = B + (size_t)(e * Ntot + n0) * KSEG;

    auto issue = [&](int c) {
        const int k0 = c * 64;
        const int st = c % NSTAGE;
        const uint32_t sA = sb + st * STB, sB = sA + TM * 128;
#pragma unroll
        for (int t = 0; t < TM / 16; t++) {            // A: TM*8 chunks / 128 thr
            int i = t * 128 + tid, row = i >> 3, c16 = i & 7;
            cpa16(sA + row * 128 + ((c16 ^ (row & 7)) << 4),
                  Ab + (size_t)row * KSEG + k0 + c16 * 8);
        }
#pragma unroll
        for (int t = 0; t < TN / 16; t++) {            // B: TN*8 chunks / 128 thr
            int i = t * 128 + tid, row = i >> 3, c16 = i & 7;
            cpa16(sB + row * 128 + ((c16 ^ (row & 7)) << 4),
                  Bb + (size_t)row * KSEG + k0 + c16 * 8);
        }
        asm volatile("cp.async.commit_group;" ::: "memory");
    };

    const int m_off = (wid >> 1) * WM;     // 2x2 warp grid
    const int n_off = (wid & 1) * WN;
    float acc[WROWS][WCOLS][4] = {};

    issue(0);
    issue(1);
    asm volatile("cp.async.wait_group 1;" ::: "memory");
    __syncthreads();

    for (int c = 0; c < NCH; ++c) {
        const int st = c % NSTAGE;
        const uint32_t sA = sb + st * STB, sB = sA + TM * 128;
#pragma unroll
        for (int kk = 0; kk < 4; ++kk) {               // 4 x k16 per 64-chunk
            uint32_t aF[WROWS][4];
#pragma unroll
            for (int i = 0; i < WROWS; ++i) {
                int row = m_off + 16 * i + (lane & 15);
                int ch  = kk * 2 + (lane >> 4);
                ldsm4(aF[i], sA + row * 128 + ((ch ^ (row & 7)) << 4));
            }
            uint32_t bF[BT16][4];
#pragma unroll
            for (int j4 = 0; j4 < BT16; ++j4) {
                int row = n_off + 16 * j4 + ((lane >> 4) << 3) + (lane & 7);
                int ch  = kk * 2 + ((lane >> 3) & 1);
                ldsm4(bF[j4], sB + row * 128 + ((ch ^ (row & 7)) << 4));
            }
#pragma unroll
            for (int i = 0; i < WROWS; ++i)
#pragma unroll
                for (int j = 0; j < WCOLS; ++j)
                    mma16816(acc[i][j], aF[i], bF[j >> 1][(j & 1) * 2], bF[j >> 1][(j & 1) * 2 + 1]);
        }
        if (c + 2 < NCH) issue(c + 2);
        else asm volatile("cp.async.commit_group;" ::: "memory");
        asm volatile("cp.async.wait_group 1;" ::: "memory");
        __syncthreads();
    }

    // ---- epilogue ----
    const int r_lane = lane >> 2;
    const int c_lane = (lane & 3) * 2;
    const float* brow = bias + (size_t)e * Ntot;
#pragma unroll
    for (int i = 0; i < WROWS; ++i) {
#pragma unroll
        for (int half = 0; half < 2; ++half) {
            const int m = m0 + m_off + 16 * i + r_lane + half * 8;
            if (PHASE == 1) {
                __half* yrow = g_Y + (size_t)(e * CAP_ + m) * H_;
#pragma unroll
                for (int j = 0; j < WCOLS; ++j) {
                    const int col = n0 + n_off + 8 * j + c_lane;
                    float v0 = acc[i][j][half * 2 + 0] + brow[col];
                    float v1 = acc[i][j][half * 2 + 1] + brow[col + 1];
                    v0 = fmaxf(v0, 0.f);
                    v1 = fmaxf(v1, 0.f);
                    *(uint32_t*)(yrow + col) = h2u(__floats2half2_rn(v0, v1));
                }
            } else {
                float* orow = outF + (size_t)(e * CAP_ + m) * D_;
#pragma unroll
                for (int j = 0; j < WCOLS; ++j) {
                    const int col = n0 + n_off + 8 * j + c_lane;
                    float2 f;
                    f.x = acc[i][j][half * 2 + 0] + brow[col];
                    f.y = acc[i][j][half * 2 + 1] + brow[col + 1];
                    *(float2*)(orow + col) = f;
                }
            }
        }
    }
}

// ---------------- launch ----------------
extern "C" void kernel_launch(void* const* d_in, const int* in_sizes, int n_in,
                              void* d_out, int out_size) {
    const float* x  = (const float*)d_in[0];   // [E, CAP, D]
    const float* w1 = (const float*)d_in[1];   // [E, H, D]
    const float* b1 = (const float*)d_in[2];   // [E, H]
    const float* w2 = (const float*)d_in[3];   // [E, H, D]
    const float* b2 = (const float*)d_in[4];   // [E, D]
    float* out = (float*)d_out;                // [E, CAP, D]

    // One-time side-stream + events (resource init only; no device memory).
    static cudaStream_t s1 = nullptr;
    static cudaEvent_t  evF = nullptr, evB = nullptr;
    if (s1 == nullptr) {
        cudaStreamCreateWithFlags(&s1, cudaStreamNonBlocking);
        cudaEventCreateWithFlags(&evF, cudaEventDisableTiming);
        cudaEventCreateWithFlags(&evB, cudaEventDisableTiming);
    }

    cudaFuncSetAttribute(gemm_mma<1>, cudaFuncAttributeMaxDynamicSharedMemorySize, SMEM_TOT);
    cudaFuncSetAttribute(gemm_mma<2>, cudaFuncAttributeMaxDynamicSharedMemorySize, SMEM_TOT);

    constexpr int EH = E_ / 2;                           // experts per half
    constexpr int GX_HALF = (EH * CAP_ * D_ / 4) / 256;  // conv_x blocks per half
    constexpr int GW_HALF = (EH * H_   * D_ / 4) / 256;  // conv_w1 blocks per half
    constexpr int G1_HALF = (CAP_ / TM) * (H_ / TN) * EH;
    constexpr int G2_FULL = (CAP_ / TM) * (D_ / TN) * E_;

    // Fork side stream at graph start.
    cudaEventRecord(evF, 0);
    cudaStreamWaitEvent(s1, evF, 0);

    // main: convert experts 0-3 (X, W1) — G1A's only dependency.
    conv_f16<0><<<GX_HALF, 256>>>(x, 0);
    conv_f16<1><<<GW_HALF, 256>>>(w1, 0);

    // side: convert experts 4-7 (X, W1) + full W2 transpose — hidden under G1A.
    conv_f16<0><<<GX_HALF, 256, 0, s1>>>(x  + (size_t)EH * CAP_ * D_, (size_t)EH * CAP_ * D_);
    conv_f16<1><<<GW_HALF, 256, 0, s1>>>(w1 + (size_t)EH * H_   * D_, (size_t)EH * H_   * D_);
    conv_w2t<<<dim3(D_ / 32, H_ / 32, E_), dim3(32, 2), 0, s1>>>(w2);
    cudaEventRecord(evB, s1);

    // G1A: experts 0-3 (starts after only the small convA).
    gemm_mma<1><<<G1_HALF, 128, SMEM_TOT>>>(b1, nullptr, 0);

    // G1B: experts 4-7 (convB long since done; also joins the side stream).
    cudaStreamWaitEvent(0, evB, 0);
    gemm_mma<1><<<G1_HALF, 128, SMEM_TOT>>>(b1, nullptr, EH);

    // G2: monolithic (needs full g_Y + g_W2T; both satisfied on main stream now).
    gemm_mma<2><<<G2_FULL, 128, SMEM_TOT>>>(b2, out, 0);
}